// round 2
// baseline (speedup 1.0000x reference)
#include <cuda_runtime.h>
#include <math.h>

#define NN 50000
#define NE 800000
#define C 96
#define TW 384            // Tcat width = 4*C
#define FW 288            // fused GEMM output width = 3*C
#define BN_EPS 1e-5f

// ---------------- scratch (device globals; no allocation allowed) ----------------
__device__ float g_Tcat[NN * TW];      // [N,384]  T0|T1|T2|T3
__device__ float g_F[NN * FW];         // [N,288]  G0|G1|G2
__device__ float g_L[NN * 3];          // logits
__device__ float g_h[NN * C];          // pre-BN output
__device__ float g_deg[NN];
__device__ float g_dis[NN];
__device__ int   g_cnt[NN];
__device__ int   g_ptr[NN + 1];
__device__ int   g_cur[NN];
__device__ int   g_bsum[64];
__device__ int   g_bsumex[64];
__device__ int   g_srow[NE];
__device__ float g_swn[NE];
__device__ int   g_erow[NE];
__device__ int   g_ecol[NE];
__device__ int   g_is64;
__device__ float g_U[TW * FW];         // combined weight
__device__ float g_A3[TW * 3];         // combined attention weight
__device__ float g_cs[3 * C];          // per-scale bias through fus_w
__device__ float g_lconst[3];          // logit constants
__device__ float g_sum[C];
__device__ float g_sumsq[C];
__device__ float g_scale[C];
__device__ float g_shift[C];

// ---------------- dtype detection: int64 edge_index has zero odd words ----------------
__global__ void k_detect(const int* __restrict__ w) {
    __shared__ int nz;
    if (threadIdx.x == 0) nz = 0;
    __syncthreads();
    // check odd 32-bit words of the first 256 pairs (values < 50000 -> high word 0 if int64)
    int v = w[threadIdx.x * 2 + 1];
    if (v != 0) atomicAdd(&nz, 1);
    __syncthreads();
    if (threadIdx.x == 0) g_is64 = (nz == 0) ? 1 : 0;
}

// ---------------- unpack edges to int32 with defensive clamping ----------------
__global__ void k_edges(const void* __restrict__ ei) {
    int e = blockIdx.x * blockDim.x + threadIdx.x;
    if (e >= NE) return;
    int r, c;
    if (g_is64) {
        const long long* p = (const long long*)ei;
        r = (int)p[e];
        c = (int)p[NE + e];
    } else {
        const int* p = (const int*)ei;
        r = p[e];
        c = p[NE + e];
    }
    if ((unsigned)r >= NN) r = 0;
    if ((unsigned)c >= NN) c = 0;
    g_erow[e] = r;
    g_ecol[e] = c;
}

// ---------------- init / zero ----------------
__global__ void k_zero() {
    int i = blockIdx.x * blockDim.x + threadIdx.x;
    if (i < NN) { g_deg[i] = 0.f; g_cnt[i] = 0; }
    if (i < TW * FW) g_U[i] = 0.f;
    if (i < TW * 3) g_A3[i] = 0.f;
    if (i < C) { g_sum[i] = 0.f; g_sumsq[i] = 0.f; }
}

__global__ void k_copy_x(const float* __restrict__ x) {
    int i = blockIdx.x * blockDim.x + threadIdx.x;
    if (i < NN * C) {
        int n = i / C, c = i - n * C;
        g_Tcat[n * TW + c] = x[i];
    }
}

// ---------------- degree + in-degree histogram ----------------
__global__ void k_deg_hist() {
    int e = blockIdx.x * blockDim.x + threadIdx.x;
    if (e >= NE) return;
    atomicAdd(&g_deg[g_erow[e]], 1.0f);
    atomicAdd(&g_cnt[g_ecol[e]], 1);
}

__global__ void k_dis() {
    int i = blockIdx.x * blockDim.x + threadIdx.x;
    if (i >= NN) return;
    float d = g_deg[i];
    g_dis[i] = (d > 0.f) ? rsqrtf(d) : 0.f;
}

// ---------------- exclusive scan of g_cnt -> g_ptr (1024 elems/block) ----------------
__global__ void k_scan_local() {
    __shared__ int wsum[8];
    int t = threadIdx.x;
    int base = blockIdx.x * 1024 + t * 4;
    int v[4];
#pragma unroll
    for (int j = 0; j < 4; j++) {
        int idx = base + j;
        v[j] = (idx < NN) ? g_cnt[idx] : 0;
    }
    int tsum = v[0] + v[1] + v[2] + v[3];
    int lane = t & 31, wid = t >> 5;
    int x = tsum;
#pragma unroll
    for (int o = 1; o < 32; o <<= 1) {
        int y = __shfl_up_sync(0xffffffffu, x, o);
        if (lane >= o) x += y;
    }
    if (lane == 31) wsum[wid] = x;
    __syncthreads();
    if (wid == 0) {
        int wv = (lane < 8) ? wsum[lane] : 0;
#pragma unroll
        for (int o = 1; o < 8; o <<= 1) {
            int y = __shfl_up_sync(0xffffffffu, wv, o);
            if (lane >= o) wv += y;
        }
        if (lane < 8) wsum[lane] = wv;  // inclusive warp sums
    }
    __syncthreads();
    int exc = x - tsum + ((wid > 0) ? wsum[wid - 1] : 0);
    int run = exc;
#pragma unroll
    for (int j = 0; j < 4; j++) {
        int idx = base + j;
        if (idx < NN) g_ptr[idx] = run;
        run += v[j];
    }
    if (t == 255) g_bsum[blockIdx.x] = run;  // block total
}

__global__ void k_scan_bsum() {
    if (threadIdx.x == 0) {
        int acc = 0;
        for (int b = 0; b < 49; b++) { int v = g_bsum[b]; g_bsumex[b] = acc; acc += v; }
    }
}

__global__ void k_scan_add() {
    int i = blockIdx.x * blockDim.x + threadIdx.x;
    if (i < NN) {
        int p = g_ptr[i] + g_bsumex[i >> 10];
        g_ptr[i] = p;
        g_cur[i] = p;
    }
    if (i == 0) g_ptr[NN] = NE;
}

// ---------------- scatter edges into CSR (grouped by col) ----------------
__global__ void k_scatter() {
    int e = blockIdx.x * blockDim.x + threadIdx.x;
    if (e >= NE) return;
    int r = g_erow[e];
    int c = g_ecol[e];
    int pos = atomicAdd(&g_cur[c], 1);
    g_srow[pos] = r;
    g_swn[pos] = -(g_dis[r] * g_dis[c]);
}

// ---------------- precompute combined weights ----------------
// U[(k*C+i), s*C+j] = sum_m w_s[k][i,m] * fus_w[(s*C+m), j]
// A3[(k*C+i), j]   += sum_m w_s[k][i,m] * attn_w[(s*C+m), j]
__global__ void k_precompU(const float* __restrict__ w2, const float* __restrict__ w3,
                           const float* __restrict__ w4, const float* __restrict__ fus_w,
                           const float* __restrict__ attn_w) {
    const int Ss[9] = {0, 0, 1, 1, 1, 2, 2, 2, 2};
    const int Kk[9] = {0, 1, 0, 1, 2, 0, 1, 2, 3};
    int b = blockIdx.x;
    int s = Ss[b], k = Kk[b];
    const float* w = ((s == 0) ? w2 : (s == 1) ? w3 : w4) + k * C * C;
    __shared__ float fusS[C * C];
    for (int i = threadIdx.x; i < C * C; i += blockDim.x)
        fusS[i] = fus_w[s * C * C + i];
    __syncthreads();
    for (int id = threadIdx.x; id < C * C; id += blockDim.x) {
        int i = id / C, j = id - (id / C) * C;
        float acc = 0.f;
#pragma unroll 8
        for (int m = 0; m < C; m++) acc += w[i * C + m] * fusS[m * C + j];
        g_U[(k * C + i) * FW + s * C + j] = acc;
    }
    for (int id = threadIdx.x; id < C * 3; id += blockDim.x) {
        int i = id / 3, j = id - (id / 3) * 3;
        float acc = 0.f;
#pragma unroll 8
        for (int m = 0; m < C; m++) acc += w[i * C + m] * attn_w[(s * C + m) * 3 + j];
        atomicAdd(&g_A3[(k * C + i) * 3 + j], acc);
    }
}

// c_s[j] = sum_m b_s[m]*fus_w[(s*C+m),j];   lconst[j] = attn_b[j] + sum_s sum_m b_s[m]*attn_w[(s*C+m),j]
__global__ void k_precomp_small(const float* __restrict__ b2, const float* __restrict__ b3,
                                const float* __restrict__ b4, const float* __restrict__ fus_w,
                                const float* __restrict__ attn_w, const float* __restrict__ attn_b) {
    int t = threadIdx.x;
    if (t < 3 * C) {
        int s = t / C, j = t - s * C;
        const float* bs = (s == 0) ? b2 : (s == 1) ? b3 : b4;
        float acc = 0.f;
        for (int m = 0; m < C; m++) acc += bs[m] * fus_w[(s * C + m) * C + j];
        g_cs[t] = acc;
    }
    if (t < 3) {
        float acc = attn_b[t];
        for (int s = 0; s < 3; s++) {
            const float* bs = (s == 0) ? b2 : (s == 1) ? b3 : b4;
            for (int m = 0; m < C; m++) acc += bs[m] * attn_w[(s * C + m) * 3 + t];
        }
        g_lconst[t] = acc;
    }
}

// ---------------- SpMM: warp per node, gather from CSR ----------------
// out slice = prop(in slice); if !first: out = 2*prop(in) - sub slice
__global__ void k_spmm(int in_off, int out_off, int sub_off, int first) {
    int warp = (blockIdx.x * blockDim.x + threadIdx.x) >> 5;
    int lane = threadIdx.x & 31;
    if (warp >= NN) return;
    int s = g_ptr[warp], e = g_ptr[warp + 1];
    float a0 = 0.f, a1 = 0.f, a2 = 0.f;
    for (int i = s; i < e; i++) {
        int r = g_srow[i];
        float w = g_swn[i];
        const float* hr = g_Tcat + (size_t)r * TW + in_off;
        a0 += w * hr[lane];
        a1 += w * hr[lane + 32];
        a2 += w * hr[lane + 64];
    }
    float* o = g_Tcat + (size_t)warp * TW + out_off;
    if (first) {
        o[lane] = a0; o[lane + 32] = a1; o[lane + 64] = a2;
    } else {
        const float* sb = g_Tcat + (size_t)warp * TW + sub_off;
        o[lane]      = 2.f * a0 - sb[lane];
        o[lane + 32] = 2.f * a1 - sb[lane + 32];
        o[lane + 64] = 2.f * a2 - sb[lane + 64];
    }
}

// ---------------- fused GEMM: F = Tcat @ U  (M=50000, K=384, N=288) ----------------
#define BM 128
#define BN 96
#define BK 16

__global__ __launch_bounds__(256) void k_gemm() {
    __shared__ float As[2][BK][BM + 4];
    __shared__ float Bs[2][BK][BN];
    int tid = threadIdx.x;
    int m0 = blockIdx.x * BM;
    int cb = blockIdx.y * BN;
    int ty = tid >> 4, tx = tid & 15;

    float acc[8][6];
#pragma unroll
    for (int i = 0; i < 8; i++)
#pragma unroll
        for (int j = 0; j < 6; j++) acc[i][j] = 0.f;

    // A loads: 128x16 = 512 float4; thread covers ids {tid, tid+256}
    int arow = tid >> 2;           // 0..63
    int aq = (tid & 3) * 4;        // k sub-offset
    // B loads: 16x96 = 384 float4; ids {tid, tid+256 (tid<128)}
    int br0 = tid / 24, bc0 = (tid % 24) * 4;
    int br1 = (tid + 256) / 24, bc1 = ((tid + 256) % 24) * 4;

    float4 A0, A1, B0, B1;
    const float4 Z = make_float4(0.f, 0.f, 0.f, 0.f);

#define LOAD_TILE(kt)                                                                  \
    {                                                                                  \
        int k0 = (kt) * BK;                                                            \
        int r0 = m0 + arow, r1 = m0 + arow + 64;                                       \
        A0 = (r0 < NN) ? *(const float4*)(g_Tcat + (size_t)r0 * TW + k0 + aq) : Z;     \
        A1 = (r1 < NN) ? *(const float4*)(g_Tcat + (size_t)r1 * TW + k0 + aq) : Z;     \
        B0 = *(const float4*)(g_U + (size_t)(br0 + k0) * FW + cb + bc0);               \
        B1 = (tid < 128) ? *(const float4*)(g_U + (size_t)(br1 + k0) * FW + cb + bc1)  \
                         : Z;                                                          \
    }
#define STORE_TILE(p)                                                                  \
    {                                                                                  \
        As[p][aq + 0][arow] = A0.x; As[p][aq + 1][arow] = A0.y;                        \
        As[p][aq + 2][arow] = A0.z; As[p][aq + 3][arow] = A0.w;                        \
        As[p][aq + 0][arow + 64] = A1.x; As[p][aq + 1][arow + 64] = A1.y;              \
        As[p][aq + 2][arow + 64] = A1.z; As[p][aq + 3][arow + 64] = A1.w;              \
        *(float4*)&Bs[p][br0][bc0] = B0;                                               \
        if (tid < 128) *(float4*)&Bs[p][br1][bc1] = B1;                                \
    }

    LOAD_TILE(0);
    STORE_TILE(0);
    __syncthreads();
    int p = 0;
    const int KT = TW / BK;  // 24
    for (int kt = 0; kt < KT; kt++) {
        if (kt + 1 < KT) LOAD_TILE(kt + 1);
#pragma unroll
        for (int kk = 0; kk < BK; kk++) {
            float a[8], b[6];
#pragma unroll
            for (int i = 0; i < 8; i++) a[i] = As[p][kk][ty * 8 + i];
#pragma unroll
            for (int j = 0; j < 6; j++) b[j] = Bs[p][kk][tx * 6 + j];
#pragma unroll
            for (int i = 0; i < 8; i++)
#pragma unroll
                for (int j = 0; j < 6; j++) acc[i][j] = fmaf(a[i], b[j], acc[i][j]);
        }
        if (kt + 1 < KT) {
            STORE_TILE(p ^ 1);
            __syncthreads();
            p ^= 1;
        }
    }
#pragma unroll
    for (int i = 0; i < 8; i++) {
        int row = m0 + ty * 8 + i;
        if (row < NN) {
#pragma unroll
            for (int j = 0; j < 6; j++)
                g_F[(size_t)row * FW + cb + tx * 6 + j] = acc[i][j];
        }
    }
#undef LOAD_TILE
#undef STORE_TILE
}

// ---------------- logits: L = Tcat @ A3 + lconst (warp per node) ----------------
__global__ void k_logits() {
    int warp = (blockIdx.x * blockDim.x + threadIdx.x) >> 5;
    int lane = threadIdx.x & 31;
    if (warp >= NN) return;
    const float* t = g_Tcat + (size_t)warp * TW;
    float l0 = 0.f, l1 = 0.f, l2 = 0.f;
    for (int k = lane; k < TW; k += 32) {
        float v = t[k];
        l0 += v * g_A3[k * 3 + 0];
        l1 += v * g_A3[k * 3 + 1];
        l2 += v * g_A3[k * 3 + 2];
    }
#pragma unroll
    for (int o = 16; o; o >>= 1) {
        l0 += __shfl_down_sync(0xffffffffu, l0, o);
        l1 += __shfl_down_sync(0xffffffffu, l1, o);
        l2 += __shfl_down_sync(0xffffffffu, l2, o);
    }
    if (lane == 0) {
        g_L[warp * 3 + 0] = l0 + g_lconst[0];
        g_L[warp * 3 + 1] = l1 + g_lconst[1];
        g_L[warp * 3 + 2] = l2 + g_lconst[2];
    }
}

// ---------------- combine: softmax-weighted sum + BN partial stats ----------------
__global__ void k_combine(const float* __restrict__ fus_b) {
    int c = threadIdx.x;  // 0..95
    float cs0 = g_cs[c], cs1 = g_cs[C + c], cs2 = g_cs[2 * C + c];
    float fb = fus_b[c];
    float lsum = 0.f, lsq = 0.f;
    for (int n = blockIdx.x; n < NN; n += gridDim.x) {
        float l0 = g_L[n * 3 + 0], l1 = g_L[n * 3 + 1], l2 = g_L[n * 3 + 2];
        float m = fmaxf(l0, fmaxf(l1, l2));
        float e0 = __expf(l0 - m), e1 = __expf(l1 - m), e2 = __expf(l2 - m);
        float inv = 1.f / (e0 + e1 + e2);
        float s0 = e0 * inv, s1 = e1 * inv, s2 = e2 * inv;
        const float* f = g_F + (size_t)n * FW;
        float h = s0 * (f[c] + cs0) + s1 * (f[C + c] + cs1) + s2 * (f[2 * C + c] + cs2) + fb;
        g_h[(size_t)n * C + c] = h;
        lsum += h;
        lsq += h * h;
    }
    atomicAdd(&g_sum[c], lsum);
    atomicAdd(&g_sumsq[c], lsq);
}

__global__ void k_bnfin(const float* __restrict__ gamma, const float* __restrict__ beta) {
    int c = threadIdx.x;
    if (c >= C) return;
    float mean = g_sum[c] / (float)NN;
    float var = g_sumsq[c] / (float)NN - mean * mean;
    var = fmaxf(var, 0.f);
    float sc = gamma[c] * rsqrtf(var + BN_EPS);
    g_scale[c] = sc;
    g_shift[c] = beta[c] - mean * sc;
}

__global__ void k_norm(float* __restrict__ out) {
    int i = blockIdx.x * blockDim.x + threadIdx.x;
    if (i >= NN * C) return;
    int c = i % C;
    out[i] = fmaxf(fmaf(g_h[i], g_scale[c], g_shift[c]), 0.f);
}

// ---------------- launch ----------------
extern "C" void kernel_launch(void* const* d_in, const int* in_sizes, int n_in,
                              void* d_out, int out_size) {
    const float* x        = (const float*)d_in[0];
    const void* ei        = d_in[1];
    const float* w2       = (const float*)d_in[2];
    const float* b2       = (const float*)d_in[3];
    const float* w3       = (const float*)d_in[4];
    const float* b3       = (const float*)d_in[5];
    const float* w4       = (const float*)d_in[6];
    const float* b4       = (const float*)d_in[7];
    const float* attn_w   = (const float*)d_in[8];
    const float* attn_b   = (const float*)d_in[9];
    const float* fus_w    = (const float*)d_in[10];
    const float* fus_b    = (const float*)d_in[11];
    const float* bn_gamma = (const float*)d_in[12];
    const float* bn_beta  = (const float*)d_in[13];
    float* out = (float*)d_out;

    k_detect<<<1, 256>>>((const int*)ei);
    k_edges<<<(NE + 255) / 256, 256>>>(ei);
    k_zero<<<(TW * FW + 255) / 256, 256>>>();
    k_copy_x<<<(NN * C + 255) / 256, 256>>>(x);
    k_deg_hist<<<(NE + 255) / 256, 256>>>();
    k_dis<<<(NN + 255) / 256, 256>>>();
    k_scan_local<<<49, 256>>>();
    k_scan_bsum<<<1, 32>>>();
    k_scan_add<<<(NN + 255) / 256, 256>>>();
    k_scatter<<<(NE + 255) / 256, 256>>>();
    k_precompU<<<9, 256>>>(w2, w3, w4, fus_w, attn_w);
    k_precomp_small<<<1, 288>>>(b2, b3, b4, fus_w, attn_w, attn_b);

    // T1 = prop(T0); T2 = 2*prop(T1) - T0; T3 = 2*prop(T2) - T1
    k_spmm<<<6250, 256>>>(0, 96, 0, 1);
    k_spmm<<<6250, 256>>>(96, 192, 0, 0);
    k_spmm<<<6250, 256>>>(192, 288, 96, 0);

    k_gemm<<<dim3((NN + BM - 1) / BM, FW / BN), 256>>>();
    k_logits<<<6250, 256>>>();
    k_combine<<<1184, 96>>>(fus_b);
    k_bnfin<<<1, 96>>>(bn_gamma, bn_beta);
    k_norm<<<(NN * C + 255) / 256, 256>>>(out);
}

// round 4
// speedup vs baseline: 1.4540x; 1.4540x over previous
#include <cuda_runtime.h>
#include <cuda_fp16.h>
#include <math.h>
#include <stdint.h>

#define NN 50000
#define NE 800000
#define C 96
#define TW 384            // Tcat width = 4*C
#define FW 288            // fused GEMM output width = 3*C
#define BN_EPS 1e-5f
#define TILES 391         // ceil(NN/128)

// ---------------- scratch (device globals; no allocation allowed) ----------------
__device__ float g_Tcat[NN * TW];
__device__ float g_F[NN * FW];
__device__ float g_L[NN * 3];
__device__ float g_h[NN * C];
__device__ float g_deg[NN];
__device__ float g_dis[NN];
__device__ int   g_cnt[NN];
__device__ int   g_ptr[NN + 1];
__device__ int   g_cur[NN];
__device__ int   g_bsum[64];
__device__ int   g_bsumex[64];
__device__ int   g_srow[NE];
__device__ float g_swn[NE];
__device__ int   g_erow[NE];
__device__ int   g_ecol[NE];
__device__ int   g_is64;
__device__ float g_U[TW * FW];
__device__ float g_A3[TW * 3];
__device__ float g_cs[3 * C];
__device__ float g_lconst[3];
__device__ float g_sum[C];
__device__ float g_sumsq[C];
__device__ float g_scale[C];
__device__ float g_shift[C];
__device__ __half g_Uf16[3 * 96 * TW];   // [nblk][96 n][384 k] n-major fp16

// ---------------- small helpers ----------------
__device__ __forceinline__ uint32_t smem_u32(const void* p) {
    uint32_t a;
    asm("{ .reg .u64 t; cvta.to.shared.u64 t, %1; cvt.u32.u64 %0, t; }" : "=r"(a) : "l"(p));
    return a;
}
#define CP16(dst, src) asm volatile("cp.async.cg.shared.global [%0], [%1], 16;" :: "r"(dst), "l"(src) : "memory")
#define CPCOMMIT()     asm volatile("cp.async.commit_group;" ::: "memory")
#define CPWAIT(n)      asm volatile("cp.async.wait_group %0;" :: "n"(n) : "memory")

__device__ __forceinline__ uint32_t cvt2h(float lo, float hi) {
    uint32_t r;
    asm("cvt.rn.f16x2.f32 %0, %1, %2;" : "=r"(r) : "f"(hi), "f"(lo));  // first src -> high half
    return r;
}

__device__ __forceinline__ void mma16816(float* d, const uint32_t* a, const uint32_t* b) {
    asm volatile(
        "mma.sync.aligned.m16n8k16.row.col.f32.f16.f16.f32 "
        "{%0,%1,%2,%3}, {%4,%5,%6,%7}, {%8,%9}, {%0,%1,%2,%3};"
        : "+f"(d[0]), "+f"(d[1]), "+f"(d[2]), "+f"(d[3])
        : "r"(a[0]), "r"(a[1]), "r"(a[2]), "r"(a[3]), "r"(b[0]), "r"(b[1]));
}

// ---------------- dtype detection ----------------
__global__ void k_detect(const int* __restrict__ w) {
    __shared__ int nz;
    if (threadIdx.x == 0) nz = 0;
    __syncthreads();
    int v = w[threadIdx.x * 2 + 1];
    if (v != 0) atomicAdd(&nz, 1);
    __syncthreads();
    if (threadIdx.x == 0) g_is64 = (nz == 0) ? 1 : 0;
}

// ---------------- init / zero ----------------
__global__ void k_zero() {
    int i = blockIdx.x * blockDim.x + threadIdx.x;
    if (i < NN) { g_deg[i] = 0.f; g_cnt[i] = 0; }
    if (i < TW * FW) g_U[i] = 0.f;
    if (i < TW * 3) g_A3[i] = 0.f;
    if (i < C) { g_sum[i] = 0.f; g_sumsq[i] = 0.f; }
}

// ---------------- unpack edges + degree histogram (fused) ----------------
__global__ void k_edges(const void* __restrict__ ei) {
    int e = blockIdx.x * blockDim.x + threadIdx.x;
    if (e >= NE) return;
    int r, c;
    if (g_is64) {
        const long long* p = (const long long*)ei;
        r = (int)p[e];
        c = (int)p[NE + e];
    } else {
        const int* p = (const int*)ei;
        r = p[e];
        c = p[NE + e];
    }
    if ((unsigned)r >= NN) r = 0;
    if ((unsigned)c >= NN) c = 0;
    g_erow[e] = r;
    g_ecol[e] = c;
    atomicAdd(&g_deg[r], 1.0f);
    atomicAdd(&g_cnt[c], 1);
}

__global__ void k_copy_x(const float* __restrict__ x) {
    int i = blockIdx.x * blockDim.x + threadIdx.x;
    if (i < NN * C) {
        int n = i / C, c = i - n * C;
        g_Tcat[n * TW + c] = x[i];
    }
}

__global__ void k_dis() {
    int i = blockIdx.x * blockDim.x + threadIdx.x;
    if (i >= NN) return;
    float d = g_deg[i];
    g_dis[i] = (d > 0.f) ? rsqrtf(d) : 0.f;
}

// ---------------- exclusive scan of g_cnt -> g_ptr ----------------
__global__ void k_scan_local() {
    __shared__ int wsum[8];
    int t = threadIdx.x;
    int base = blockIdx.x * 1024 + t * 4;
    int v[4];
#pragma unroll
    for (int j = 0; j < 4; j++) {
        int idx = base + j;
        v[j] = (idx < NN) ? g_cnt[idx] : 0;
    }
    int tsum = v[0] + v[1] + v[2] + v[3];
    int lane = t & 31, wid = t >> 5;
    int x = tsum;
#pragma unroll
    for (int o = 1; o < 32; o <<= 1) {
        int y = __shfl_up_sync(0xffffffffu, x, o);
        if (lane >= o) x += y;
    }
    if (lane == 31) wsum[wid] = x;
    __syncthreads();
    if (wid == 0) {
        int wv = (lane < 8) ? wsum[lane] : 0;
#pragma unroll
        for (int o = 1; o < 8; o <<= 1) {
            int y = __shfl_up_sync(0xffffffffu, wv, o);
            if (lane >= o) wv += y;
        }
        if (lane < 8) wsum[lane] = wv;
    }
    __syncthreads();
    int exc = x - tsum + ((wid > 0) ? wsum[wid - 1] : 0);
    int run = exc;
#pragma unroll
    for (int j = 0; j < 4; j++) {
        int idx = base + j;
        if (idx < NN) g_ptr[idx] = run;
        run += v[j];
    }
    if (t == 255) g_bsum[blockIdx.x] = run;
}

__global__ void k_scan_bsum() {
    if (threadIdx.x == 0) {
        int acc = 0;
        for (int b = 0; b < 49; b++) { int v = g_bsum[b]; g_bsumex[b] = acc; acc += v; }
    }
}

__global__ void k_scan_add() {
    int i = blockIdx.x * blockDim.x + threadIdx.x;
    if (i < NN) {
        int p = g_ptr[i] + g_bsumex[i >> 10];
        g_ptr[i] = p;
        g_cur[i] = p;
    }
    if (i == 0) g_ptr[NN] = NE;
}

__global__ void k_scatter() {
    int e = blockIdx.x * blockDim.x + threadIdx.x;
    if (e >= NE) return;
    int r = g_erow[e];
    int c = g_ecol[e];
    int pos = atomicAdd(&g_cur[c], 1);
    g_srow[pos] = r;
    g_swn[pos] = -(g_dis[r] * g_dis[c]);
}

// ---------------- precompute combined weights ----------------
__global__ void k_precompU(const float* __restrict__ w2, const float* __restrict__ w3,
                           const float* __restrict__ w4, const float* __restrict__ fus_w,
                           const float* __restrict__ attn_w) {
    const int Ss[9] = {0, 0, 1, 1, 1, 2, 2, 2, 2};
    const int Kk[9] = {0, 1, 0, 1, 2, 0, 1, 2, 3};
    int b = blockIdx.x;
    int s = Ss[b], k = Kk[b];
    const float* w = ((s == 0) ? w2 : (s == 1) ? w3 : w4) + k * C * C;
    __shared__ float fusS[C * C];
    for (int i = threadIdx.x; i < C * C; i += blockDim.x)
        fusS[i] = fus_w[s * C * C + i];
    __syncthreads();
    for (int id = threadIdx.x; id < C * C; id += blockDim.x) {
        int i = id / C, j = id - (id / C) * C;
        float acc = 0.f;
#pragma unroll 8
        for (int m = 0; m < C; m++) acc += w[i * C + m] * fusS[m * C + j];
        g_U[(k * C + i) * FW + s * C + j] = acc;
    }
    for (int id = threadIdx.x; id < C * 3; id += blockDim.x) {
        int i = id / 3, j = id - (id / 3) * 3;
        float acc = 0.f;
#pragma unroll 8
        for (int m = 0; m < C; m++) acc += w[i * C + m] * attn_w[(s * C + m) * 3 + j];
        atomicAdd(&g_A3[(k * C + i) * 3 + j], acc);
    }
}

__global__ void k_precomp_small(const float* __restrict__ b2, const float* __restrict__ b3,
                                const float* __restrict__ b4, const float* __restrict__ fus_w,
                                const float* __restrict__ attn_w, const float* __restrict__ attn_b) {
    int t = threadIdx.x;
    if (t < 3 * C) {
        int s = t / C, j = t - s * C;
        const float* bs = (s == 0) ? b2 : (s == 1) ? b3 : b4;
        float acc = 0.f;
        for (int m = 0; m < C; m++) acc += bs[m] * fus_w[(s * C + m) * C + j];
        g_cs[t] = acc;
    }
    if (t < 3) {
        float acc = attn_b[t];
        for (int s = 0; s < 3; s++) {
            const float* bs = (s == 0) ? b2 : (s == 1) ? b3 : b4;
            for (int m = 0; m < C; m++) acc += bs[m] * attn_w[(s * C + m) * 3 + t];
        }
        g_lconst[t] = acc;
    }
}

// ---------------- convert U to fp16, n-major [nblk][96][384] ----------------
__global__ void k_splitU16() {
    int id = blockIdx.x * blockDim.x + threadIdx.x;
    if (id >= TW * FW) return;
    int n = id % FW, k = id / FW;
    float v = g_U[k * FW + n];
    int nblk = n / 96, nl = n - nblk * 96;
    g_Uf16[((size_t)nblk * 96 + nl) * TW + k] = __float2half(v);
}

// ---------------- SpMM: warp per node, gather from CSR ----------------
__global__ void k_spmm(int in_off, int out_off, int sub_off, int first) {
    int warp = (blockIdx.x * blockDim.x + threadIdx.x) >> 5;
    int lane = threadIdx.x & 31;
    if (warp >= NN) return;
    int s = g_ptr[warp], e = g_ptr[warp + 1];
    float a0 = 0.f, a1 = 0.f, a2 = 0.f;
    for (int i = s; i < e; i++) {
        int r = g_srow[i];
        float w = g_swn[i];
        const float* hr = g_Tcat + (size_t)r * TW + in_off;
        a0 += w * hr[lane];
        a1 += w * hr[lane + 32];
        a2 += w * hr[lane + 64];
    }
    float* o = g_Tcat + (size_t)warp * TW + out_off;
    if (first) {
        o[lane] = a0; o[lane + 32] = a1; o[lane + 64] = a2;
    } else {
        const float* sb = g_Tcat + (size_t)warp * TW + sub_off;
        o[lane]      = 2.f * a0 - sb[lane];
        o[lane + 32] = 2.f * a1 - sb[lane + 32];
        o[lane + 64] = 2.f * a2 - sb[lane + 64];
    }
}

// ---------------- tensor-core GEMM (mma.sync fp16): F = Tcat @ U ----------------
// CTA tile 128(M) x 96(N); grid (3 nblk, 391 mtile); 256 threads = 8 warps (4x2);
// warp tile 32x48 = 2 m16 x 6 n8 tiles. K = 6 chunks of 64, cp.async double buffered.
// A fp32 in SMEM [2][128][68] (pad 4), converted to fp16 at fragment load.
// B fp16 n-major [2][96][72] (pad 8).
#define SM_A_BYTES (2 * 128 * 68 * 4)     // 69632
#define SM_B_BYTES (2 * 96 * 72 * 2)      // 27648
#define GEMM_SMEM (SM_A_BYTES + SM_B_BYTES)

__global__ void __launch_bounds__(256, 2) k_gemm16() {
    extern __shared__ unsigned char dyn[];
    float* As = (float*)dyn;                          // [2][128][68]
    __half* Bs = (__half*)(dyn + SM_A_BYTES);         // [2][96][72]
    uint32_t smA = smem_u32(As);
    uint32_t smB = smem_u32(Bs);

    int tid = threadIdx.x;
    int lane = tid & 31, wid = tid >> 5;
    int wm = wid & 3, wn = wid >> 2;
    int gid = lane >> 2, tq = lane & 3;
    int nblk = blockIdx.x;
    int m0 = blockIdx.y * 128;

#define LOAD_A(chunk, buf)                                                                 \
    {                                                                                      \
        _Pragma("unroll") for (int i = 0; i < 8; i++) {                                    \
            int idx = tid + i * 256;                                                       \
            int row = idx >> 4, seg = idx & 15;                                            \
            int srow = m0 + row; if (srow >= NN) srow = NN - 1;                            \
            const float* src = g_Tcat + (size_t)srow * TW + (chunk) * 64 + seg * 4;        \
            uint32_t dst = smA + (((buf) * 128 + row) * 68 + seg * 4) * 4;                 \
            CP16(dst, src);                                                                \
        }                                                                                  \
    }
#define LOAD_B(chunk, buf)                                                                 \
    {                                                                                      \
        _Pragma("unroll") for (int i = 0; i < 3; i++) {                                    \
            int idx = tid + i * 256;                                                       \
            int row = idx >> 3, seg = idx & 7;                                             \
            const __half* src = g_Uf16 + ((size_t)nblk * 96 + row) * TW + (chunk) * 64 + seg * 8; \
            uint32_t dst = smB + (((buf) * 96 + row) * 72 + seg * 8) * 2;                  \
            CP16(dst, src);                                                                \
        }                                                                                  \
    }

    float acc[2][6][4];
#pragma unroll
    for (int mt = 0; mt < 2; mt++)
#pragma unroll
        for (int nt = 0; nt < 6; nt++)
#pragma unroll
            for (int q = 0; q < 4; q++) acc[mt][nt][q] = 0.f;

    LOAD_A(0, 0);
    LOAD_B(0, 0);
    CPCOMMIT();

    for (int c = 0; c < 6; c++) {
        int buf = c & 1;
        if (c + 1 < 6) {
            LOAD_A(c + 1, buf ^ 1);
            LOAD_B(c + 1, buf ^ 1);
            CPCOMMIT();
            CPWAIT(1);
        } else {
            CPWAIT(0);
        }
        __syncthreads();

        const float* Ab = As + (size_t)buf * 128 * 68;
        const __half* Bb = Bs + (size_t)buf * 96 * 72;
#pragma unroll
        for (int k16 = 0; k16 < 4; k16++) {
            uint32_t afr[2][4];
#pragma unroll
            for (int mt = 0; mt < 2; mt++) {
                int r = wm * 32 + mt * 16 + gid;
                int kk = k16 * 16 + tq * 2;
                float2 v0 = *(const float2*)(Ab + r * 68 + kk);
                float2 v1 = *(const float2*)(Ab + (r + 8) * 68 + kk);
                float2 v2 = *(const float2*)(Ab + r * 68 + kk + 8);
                float2 v3 = *(const float2*)(Ab + (r + 8) * 68 + kk + 8);
                afr[mt][0] = cvt2h(v0.x, v0.y);
                afr[mt][1] = cvt2h(v1.x, v1.y);
                afr[mt][2] = cvt2h(v2.x, v2.y);
                afr[mt][3] = cvt2h(v3.x, v3.y);
            }
            uint32_t bfr[6][2];
#pragma unroll
            for (int nt = 0; nt < 6; nt++) {
                int n = wn * 48 + nt * 8 + gid;
                int kk = k16 * 16 + tq * 2;
                bfr[nt][0] = *(const uint32_t*)(Bb + n * 72 + kk);
                bfr[nt][1] = *(const uint32_t*)(Bb + n * 72 + kk + 8);
            }
#pragma unroll
            for (int mt = 0; mt < 2; mt++)
#pragma unroll
                for (int nt = 0; nt < 6; nt++)
                    mma16816(acc[mt][nt], afr[mt], bfr[nt]);
        }
        __syncthreads();
    }

    // epilogue: direct float2 stores
#pragma unroll
    for (int mt = 0; mt < 2; mt++) {
        int r = m0 + wm * 32 + mt * 16 + gid;
#pragma unroll
        for (int nt = 0; nt < 6; nt++) {
            int cc = nblk * 96 + wn * 48 + nt * 8 + tq * 2;
            if (r < NN)
                *(float2*)(g_F + (size_t)r * FW + cc) = make_float2(acc[mt][nt][0], acc[mt][nt][1]);
            if (r + 8 < NN)
                *(float2*)(g_F + (size_t)(r + 8) * FW + cc) = make_float2(acc[mt][nt][2], acc[mt][nt][3]);
        }
    }
#undef LOAD_A
#undef LOAD_B
}

// ---------------- logits: L = Tcat @ A3 + lconst ----------------
__global__ void k_logits() {
    int warp = (blockIdx.x * blockDim.x + threadIdx.x) >> 5;
    int lane = threadIdx.x & 31;
    if (warp >= NN) return;
    const float* t = g_Tcat + (size_t)warp * TW;
    float l0 = 0.f, l1 = 0.f, l2 = 0.f;
    for (int k = lane; k < TW; k += 32) {
        float v = t[k];
        l0 += v * g_A3[k * 3 + 0];
        l1 += v * g_A3[k * 3 + 1];
        l2 += v * g_A3[k * 3 + 2];
    }
#pragma unroll
    for (int o = 16; o; o >>= 1) {
        l0 += __shfl_down_sync(0xffffffffu, l0, o);
        l1 += __shfl_down_sync(0xffffffffu, l1, o);
        l2 += __shfl_down_sync(0xffffffffu, l2, o);
    }
    if (lane == 0) {
        g_L[warp * 3 + 0] = l0 + g_lconst[0];
        g_L[warp * 3 + 1] = l1 + g_lconst[1];
        g_L[warp * 3 + 2] = l2 + g_lconst[2];
    }
}

// ---------------- combine + BN stats ----------------
__global__ void k_combine(const float* __restrict__ fus_b) {
    int c = threadIdx.x;
    float cs0 = g_cs[c], cs1 = g_cs[C + c], cs2 = g_cs[2 * C + c];
    float fb = fus_b[c];
    float lsum = 0.f, lsq = 0.f;
    for (int n = blockIdx.x; n < NN; n += gridDim.x) {
        float l0 = g_L[n * 3 + 0], l1 = g_L[n * 3 + 1], l2 = g_L[n * 3 + 2];
        float m = fmaxf(l0, fmaxf(l1, l2));
        float e0 = __expf(l0 - m), e1 = __expf(l1 - m), e2 = __expf(l2 - m);
        float inv = 1.f / (e0 + e1 + e2);
        float s0 = e0 * inv, s1 = e1 * inv, s2 = e2 * inv;
        const float* f = g_F + (size_t)n * FW;
        float h = s0 * (f[c] + cs0) + s1 * (f[C + c] + cs1) + s2 * (f[2 * C + c] + cs2) + fb;
        g_h[(size_t)n * C + c] = h;
        lsum += h;
        lsq += h * h;
    }
    atomicAdd(&g_sum[c], lsum);
    atomicAdd(&g_sumsq[c], lsq);
}

__global__ void k_bnfin(const float* __restrict__ gamma, const float* __restrict__ beta) {
    int c = threadIdx.x;
    if (c >= C) return;
    float mean = g_sum[c] / (float)NN;
    float var = g_sumsq[c] / (float)NN - mean * mean;
    var = fmaxf(var, 0.f);
    float sc = gamma[c] * rsqrtf(var + BN_EPS);
    g_scale[c] = sc;
    g_shift[c] = beta[c] - mean * sc;
}

__global__ void k_norm(float* __restrict__ out) {
    int i = blockIdx.x * blockDim.x + threadIdx.x;
    if (i >= NN * C) return;
    int c = i % C;
    out[i] = fmaxf(fmaf(g_h[i], g_scale[c], g_shift[c]), 0.f);
}

// ---------------- launch ----------------
extern "C" void kernel_launch(void* const* d_in, const int* in_sizes, int n_in,
                              void* d_out, int out_size) {
    const float* x        = (const float*)d_in[0];
    const void* ei        = d_in[1];
    const float* w2       = (const float*)d_in[2];
    const float* b2       = (const float*)d_in[3];
    const float* w3       = (const float*)d_in[4];
    const float* b3       = (const float*)d_in[5];
    const float* w4       = (const float*)d_in[6];
    const float* b4       = (const float*)d_in[7];
    const float* attn_w   = (const float*)d_in[8];
    const float* attn_b   = (const float*)d_in[9];
    const float* fus_w    = (const float*)d_in[10];
    const float* fus_b    = (const float*)d_in[11];
    const float* bn_gamma = (const float*)d_in[12];
    const float* bn_beta  = (const float*)d_in[13];
    float* out = (float*)d_out;

    static int smem_set = 0;
    if (!smem_set) {
        cudaFuncSetAttribute(k_gemm16, cudaFuncAttributeMaxDynamicSharedMemorySize, GEMM_SMEM);
        smem_set = 1;
    }

    k_detect<<<1, 256>>>((const int*)ei);
    k_zero<<<(TW * FW + 255) / 256, 256>>>();
    k_edges<<<(NE + 255) / 256, 256>>>(ei);
    k_copy_x<<<(NN * C + 255) / 256, 256>>>(x);
    k_dis<<<(NN + 255) / 256, 256>>>();
    k_scan_local<<<49, 256>>>();
    k_scan_bsum<<<1, 32>>>();
    k_scan_add<<<(NN + 255) / 256, 256>>>();
    k_scatter<<<(NE + 255) / 256, 256>>>();
    k_precompU<<<9, 256>>>(w2, w3, w4, fus_w, attn_w);
    k_precomp_small<<<1, 288>>>(b2, b3, b4, fus_w, attn_w, attn_b);
    k_splitU16<<<(TW * FW + 255) / 256, 256>>>();

    // T1 = prop(T0); T2 = 2*prop(T1) - T0; T3 = 2*prop(T2) - T1
    k_spmm<<<6250, 256>>>(0, 96, 0, 1);
    k_spmm<<<6250, 256>>>(96, 192, 0, 0);
    k_spmm<<<6250, 256>>>(192, 288, 96, 0);

    k_gemm16<<<dim3(3, TILES), 256, GEMM_SMEM>>>();

    k_logits<<<6250, 256>>>();
    k_combine<<<1184, 96>>>(fus_b);
    k_bnfin<<<1, 96>>>(bn_gamma, bn_beta);
    k_norm<<<(NN * C + 255) / 256, 256>>>(out);
}

// round 5
// speedup vs baseline: 1.8010x; 1.2387x over previous
#include <cuda_runtime.h>
#include <cuda_fp16.h>
#include <math.h>
#include <stdint.h>

#define NN 50000
#define NE 800000
#define C 96
#define TCW 288           // Tc width = 3*C (T1|T2|T3); T0 lives in x
#define KW 384            // total K = 4*C
#define FW 288            // fused GEMM output width = 3*C
#define BN_EPS 1e-5f
#define TILES 391         // ceil(NN/128)

// ---------------- scratch (device globals; no allocation allowed) ----------------
__device__ float g_Tc[NN * TCW];       // [N,288]  T1|T2|T3
__device__ float g_h[NN * C];          // pre-BN output
__device__ float g_deg[NN];
__device__ float g_dis[NN];
__device__ int   g_cnt[NN];
__device__ int   g_ptr[NN + 1];
__device__ int   g_cur[NN];
__device__ int   g_bsum[64];
__device__ int   g_bsumex[64];
__device__ int   g_srow[NE];
__device__ float g_swn[NE];
__device__ int   g_erow[NE];
__device__ int   g_ecol[NE];
__device__ int   g_is64;
__device__ float g_U[KW * FW];
__device__ float g_A3[KW * 3];
__device__ float g_cs[3 * C];
__device__ float g_lconst[3];
__device__ float g_sum[C];
__device__ float g_sumsq[C];
__device__ float g_scale[C];
__device__ float g_shift[C];
__device__ __half g_Uf16[FW * KW];     // n-major [288 n][384 k] fp16

// ---------------- small helpers ----------------
__device__ __forceinline__ uint32_t smem_u32(const void* p) {
    uint32_t a;
    asm("{ .reg .u64 t; cvta.to.shared.u64 t, %1; cvt.u32.u64 %0, t; }" : "=r"(a) : "l"(p));
    return a;
}
#define CP16(dst, src) asm volatile("cp.async.cg.shared.global [%0], [%1], 16;" :: "r"(dst), "l"(src) : "memory")
#define CPCOMMIT()     asm volatile("cp.async.commit_group;" ::: "memory")
#define CPWAIT(n)      asm volatile("cp.async.wait_group %0;" :: "n"(n) : "memory")

__device__ __forceinline__ uint32_t cvt2h(float lo, float hi) {
    uint32_t r;
    asm("cvt.rn.f16x2.f32 %0, %1, %2;" : "=r"(r) : "f"(hi), "f"(lo));
    return r;
}

__device__ __forceinline__ void mma16816(float* d, const uint32_t* a, const uint32_t* b) {
    asm volatile(
        "mma.sync.aligned.m16n8k16.row.col.f32.f16.f16.f32 "
        "{%0,%1,%2,%3}, {%4,%5,%6,%7}, {%8,%9}, {%0,%1,%2,%3};"
        : "+f"(d[0]), "+f"(d[1]), "+f"(d[2]), "+f"(d[3])
        : "r"(a[0]), "r"(a[1]), "r"(a[2]), "r"(a[3]), "r"(b[0]), "r"(b[1]));
}

// ---------------- dtype detection ----------------
__global__ void k_detect(const int* __restrict__ w) {
    __shared__ int nz;
    if (threadIdx.x == 0) nz = 0;
    __syncthreads();
    int v = w[threadIdx.x * 2 + 1];
    if (v != 0) atomicAdd(&nz, 1);
    __syncthreads();
    if (threadIdx.x == 0) g_is64 = (nz == 0) ? 1 : 0;
}

// ---------------- init / zero ----------------
__global__ void k_zero() {
    int i = blockIdx.x * blockDim.x + threadIdx.x;
    if (i < NN) { g_deg[i] = 0.f; g_cnt[i] = 0; }
    if (i < KW * FW) g_U[i] = 0.f;
    if (i < KW * 3) g_A3[i] = 0.f;
    if (i < C) { g_sum[i] = 0.f; g_sumsq[i] = 0.f; }
}

// ---------------- unpack edges + degree histogram (fused) ----------------
__global__ void k_edges(const void* __restrict__ ei) {
    int e = blockIdx.x * blockDim.x + threadIdx.x;
    if (e >= NE) return;
    int r, c;
    if (g_is64) {
        const long long* p = (const long long*)ei;
        r = (int)p[e];
        c = (int)p[NE + e];
    } else {
        const int* p = (const int*)ei;
        r = p[e];
        c = p[NE + e];
    }
    if ((unsigned)r >= NN) r = 0;
    if ((unsigned)c >= NN) c = 0;
    g_erow[e] = r;
    g_ecol[e] = c;
    atomicAdd(&g_deg[r], 1.0f);
    atomicAdd(&g_cnt[c], 1);
}

__global__ void k_dis() {
    int i = blockIdx.x * blockDim.x + threadIdx.x;
    if (i >= NN) return;
    float d = g_deg[i];
    g_dis[i] = (d > 0.f) ? rsqrtf(d) : 0.f;
}

// ---------------- exclusive scan of g_cnt -> g_ptr ----------------
__global__ void k_scan_local() {
    __shared__ int wsum[8];
    int t = threadIdx.x;
    int base = blockIdx.x * 1024 + t * 4;
    int v[4];
#pragma unroll
    for (int j = 0; j < 4; j++) {
        int idx = base + j;
        v[j] = (idx < NN) ? g_cnt[idx] : 0;
    }
    int tsum = v[0] + v[1] + v[2] + v[3];
    int lane = t & 31, wid = t >> 5;
    int x = tsum;
#pragma unroll
    for (int o = 1; o < 32; o <<= 1) {
        int y = __shfl_up_sync(0xffffffffu, x, o);
        if (lane >= o) x += y;
    }
    if (lane == 31) wsum[wid] = x;
    __syncthreads();
    if (wid == 0) {
        int wv = (lane < 8) ? wsum[lane] : 0;
#pragma unroll
        for (int o = 1; o < 8; o <<= 1) {
            int y = __shfl_up_sync(0xffffffffu, wv, o);
            if (lane >= o) wv += y;
        }
        if (lane < 8) wsum[lane] = wv;
    }
    __syncthreads();
    int exc = x - tsum + ((wid > 0) ? wsum[wid - 1] : 0);
    int run = exc;
#pragma unroll
    for (int j = 0; j < 4; j++) {
        int idx = base + j;
        if (idx < NN) g_ptr[idx] = run;
        run += v[j];
    }
    if (t == 255) g_bsum[blockIdx.x] = run;
}

__global__ void k_scan_bsum() {
    if (threadIdx.x == 0) {
        int acc = 0;
        for (int b = 0; b < 49; b++) { int v = g_bsum[b]; g_bsumex[b] = acc; acc += v; }
    }
}

__global__ void k_scan_add() {
    int i = blockIdx.x * blockDim.x + threadIdx.x;
    if (i < NN) {
        int p = g_ptr[i] + g_bsumex[i >> 10];
        g_ptr[i] = p;
        g_cur[i] = p;
    }
    if (i == 0) g_ptr[NN] = NE;
}

__global__ void k_scatter() {
    int e = blockIdx.x * blockDim.x + threadIdx.x;
    if (e >= NE) return;
    int r = g_erow[e];
    int c = g_ecol[e];
    int pos = atomicAdd(&g_cur[c], 1);
    g_srow[pos] = r;
    g_swn[pos] = -(g_dis[r] * g_dis[c]);
}

// ---------------- precompute combined weights ----------------
__global__ void k_precompU(const float* __restrict__ w2, const float* __restrict__ w3,
                           const float* __restrict__ w4, const float* __restrict__ fus_w,
                           const float* __restrict__ attn_w) {
    const int Ss[9] = {0, 0, 1, 1, 1, 2, 2, 2, 2};
    const int Kk[9] = {0, 1, 0, 1, 2, 0, 1, 2, 3};
    int b = blockIdx.x;
    int s = Ss[b], k = Kk[b];
    const float* w = ((s == 0) ? w2 : (s == 1) ? w3 : w4) + k * C * C;
    __shared__ float fusS[C * C];
    for (int i = threadIdx.x; i < C * C; i += blockDim.x)
        fusS[i] = fus_w[s * C * C + i];
    __syncthreads();
    for (int id = threadIdx.x; id < C * C; id += blockDim.x) {
        int i = id / C, j = id - (id / C) * C;
        float acc = 0.f;
#pragma unroll 8
        for (int m = 0; m < C; m++) acc += w[i * C + m] * fusS[m * C + j];
        g_U[(k * C + i) * FW + s * C + j] = acc;
    }
    for (int id = threadIdx.x; id < C * 3; id += blockDim.x) {
        int i = id / 3, j = id - (id / 3) * 3;
        float acc = 0.f;
#pragma unroll 8
        for (int m = 0; m < C; m++) acc += w[i * C + m] * attn_w[(s * C + m) * 3 + j];
        atomicAdd(&g_A3[(k * C + i) * 3 + j], acc);
    }
}

__global__ void k_precomp_small(const float* __restrict__ b2, const float* __restrict__ b3,
                                const float* __restrict__ b4, const float* __restrict__ fus_w,
                                const float* __restrict__ attn_w, const float* __restrict__ attn_b) {
    int t = threadIdx.x;
    if (t < 3 * C) {
        int s = t / C, j = t - s * C;
        const float* bs = (s == 0) ? b2 : (s == 1) ? b3 : b4;
        float acc = 0.f;
        for (int m = 0; m < C; m++) acc += bs[m] * fus_w[(s * C + m) * C + j];
        g_cs[t] = acc;
    }
    if (t < 3) {
        float acc = attn_b[t];
        for (int s = 0; s < 3; s++) {
            const float* bs = (s == 0) ? b2 : (s == 1) ? b3 : b4;
            for (int m = 0; m < C; m++) acc += bs[m] * attn_w[(s * C + m) * 3 + t];
        }
        g_lconst[t] = acc;
    }
}

// ---------------- convert U to fp16, n-major [288][384] ----------------
__global__ void k_splitU16() {
    int id = blockIdx.x * blockDim.x + threadIdx.x;
    if (id >= KW * FW) return;
    int n = id % FW, k = id / FW;
    g_Uf16[(size_t)n * KW + k] = __float2half(g_U[k * FW + n]);
}

// ---------------- SpMM: warp per node, gather from CSR ----------------
__global__ void k_spmm(const float* __restrict__ in, int inw,
                       const float* __restrict__ sub, int subw,
                       float* __restrict__ out, int first) {
    int warp = (blockIdx.x * blockDim.x + threadIdx.x) >> 5;
    int lane = threadIdx.x & 31;
    if (warp >= NN) return;
    int s = g_ptr[warp], e = g_ptr[warp + 1];
    float a0 = 0.f, a1 = 0.f, a2 = 0.f;
    for (int i = s; i < e; i++) {
        int r = g_srow[i];
        float w = g_swn[i];
        const float* hr = in + (size_t)r * inw;
        a0 += w * hr[lane];
        a1 += w * hr[lane + 32];
        a2 += w * hr[lane + 64];
    }
    float* o = out + (size_t)warp * TCW;
    if (first) {
        o[lane] = a0; o[lane + 32] = a1; o[lane + 64] = a2;
    } else {
        const float* sb = sub + (size_t)warp * subw;
        o[lane]      = 2.f * a0 - sb[lane];
        o[lane + 32] = 2.f * a1 - sb[lane + 32];
        o[lane + 64] = 2.f * a2 - sb[lane + 64];
    }
}

// ---------------- fused GEMM + logits + softmax combine + BN partials ----------------
// CTA tile 128(M) x 288(N), 512 threads = 16 warps (4m x 4n), warp tile 32x72.
// A: [2][128][68] fp32 (cvt to fp16 at frag load).  B: [2][288][72] fp16.
// K = 6 chunks of 64; k<96 from x, else from g_Tc.
#define SM_A_OFF 0
#define SM_A_BYTES (2 * 128 * 68 * 4)                       // 69632
#define SM_B_OFF SM_A_BYTES
#define SM_B_BYTES (2 * 288 * 72 * 2)                       // 82944
#define SM_A3_OFF (SM_B_OFF + SM_B_BYTES)                   // 152576
#define SM_A3_BYTES (KW * 3 * 4)                            // 4608
#define SM_LS_OFF (SM_A3_OFF + SM_A3_BYTES)                 // 157184
#define SM_WS_OFF (SM_LS_OFF + 128 * 3 * 4)                 // 158720
#define FUSED_SMEM (SM_WS_OFF + 128 * 3 * 4)                // 160256
#define STG_PITCH 292

__global__ void __launch_bounds__(512, 1) k_fused(const float* __restrict__ x,
                                                  const float* __restrict__ fus_b) {
    extern __shared__ unsigned char dyn[];
    float* As = (float*)(dyn + SM_A_OFF);         // [2][128][68]
    __half* Bs = (__half*)(dyn + SM_B_OFF);       // [2][288][72]
    float* A3s = (float*)(dyn + SM_A3_OFF);       // [384][3]
    float* Ls = (float*)(dyn + SM_LS_OFF);        // [128][3]
    float* Ws = (float*)(dyn + SM_WS_OFF);        // [128][3]
    float* stage = (float*)dyn;                   // [128][292] (epilogue, overlaps A/B)
    float* bnS = A3s;                             // [192] (epilogue, overlaps A3s)
    uint32_t smA = smem_u32(As);
    uint32_t smB = smem_u32(Bs);

    int tid = threadIdx.x;
    int lane = tid & 31, wid = tid >> 5;
    int wm = wid & 3, wn = wid >> 2;
    int gid = lane >> 2, tq = lane & 3;
    int m0 = blockIdx.x * 128;

    // A3 -> smem
    for (int i = tid; i < KW * 3; i += 512) A3s[i] = g_A3[i];

#define LOAD_A(chunk, buf)                                                                  \
    {                                                                                       \
        _Pragma("unroll") for (int i = 0; i < 4; i++) {                                     \
            int idx = tid + i * 512;                                                        \
            int row = idx >> 4, seg = idx & 15;                                             \
            int srow = m0 + row; if (srow >= NN) srow = NN - 1;                             \
            int kcol = (chunk) * 64 + seg * 4;                                              \
            const float* src = (kcol < 96) ? (x + (size_t)srow * 96 + kcol)                 \
                                           : (g_Tc + (size_t)srow * TCW + (kcol - 96));     \
            uint32_t dst = smA + (((buf) * 128 + row) * 68 + seg * 4) * 4;                  \
            CP16(dst, src);                                                                 \
        }                                                                                   \
    }
#define LOAD_B(chunk, buf)                                                                  \
    {                                                                                       \
        _Pragma("unroll") for (int i = 0; i < 5; i++) {                                     \
            int idx = tid + i * 512;                                                        \
            if (idx < 2304) {                                                               \
                int row = idx >> 3, seg = idx & 7;                                          \
                const __half* src = g_Uf16 + (size_t)row * KW + (chunk) * 64 + seg * 8;     \
                uint32_t dst = smB + (((buf) * 288 + row) * 72 + seg * 8) * 2;              \
                CP16(dst, src);                                                             \
            }                                                                               \
        }                                                                                   \
    }

    float acc[2][9][4];
#pragma unroll
    for (int mt = 0; mt < 2; mt++)
#pragma unroll
        for (int nt = 0; nt < 9; nt++)
#pragma unroll
            for (int q = 0; q < 4; q++) acc[mt][nt][q] = 0.f;
    float Lacc = 0.f;
    int lr = tid / 3, lj = tid - (tid / 3) * 3;   // logits assignment (tid<384)

    LOAD_A(0, 0);
    LOAD_B(0, 0);
    CPCOMMIT();

    for (int c = 0; c < 6; c++) {
        int buf = c & 1;
        if (c + 1 < 6) {
            LOAD_A(c + 1, buf ^ 1);
            LOAD_B(c + 1, buf ^ 1);
            CPCOMMIT();
            CPWAIT(1);
        } else {
            CPWAIT(0);
        }
        __syncthreads();

        const float* Ab = As + (size_t)buf * 128 * 68;
        const __half* Bb = Bs + (size_t)buf * 288 * 72;
#pragma unroll
        for (int k16 = 0; k16 < 4; k16++) {
            uint32_t afr[2][4];
#pragma unroll
            for (int mt = 0; mt < 2; mt++) {
                int r = wm * 32 + mt * 16 + gid;
                int kk = k16 * 16 + tq * 2;
                float2 v0 = *(const float2*)(Ab + r * 68 + kk);
                float2 v1 = *(const float2*)(Ab + (r + 8) * 68 + kk);
                float2 v2 = *(const float2*)(Ab + r * 68 + kk + 8);
                float2 v3 = *(const float2*)(Ab + (r + 8) * 68 + kk + 8);
                afr[mt][0] = cvt2h(v0.x, v0.y);
                afr[mt][1] = cvt2h(v1.x, v1.y);
                afr[mt][2] = cvt2h(v2.x, v2.y);
                afr[mt][3] = cvt2h(v3.x, v3.y);
            }
            uint32_t bfr[9][2];
#pragma unroll
            for (int nt = 0; nt < 9; nt++) {
                int n = wn * 72 + nt * 8 + gid;
                int kk = k16 * 16 + tq * 2;
                bfr[nt][0] = *(const uint32_t*)(Bb + n * 72 + kk);
                bfr[nt][1] = *(const uint32_t*)(Bb + n * 72 + kk + 8);
            }
#pragma unroll
            for (int mt = 0; mt < 2; mt++)
#pragma unroll
                for (int nt = 0; nt < 9; nt++)
                    mma16816(acc[mt][nt], afr[mt], bfr[nt]);
        }
        // fp32 logits on the same A chunk
        if (tid < 384) {
            const float* Ar = Ab + lr * 68;
            const float* A3c = A3s + c * 64 * 3 + lj;
#pragma unroll 8
            for (int kk = 0; kk < 64; kk++) Lacc += Ar[kk] * A3c[kk * 3];
        }
        __syncthreads();
    }

    // ---- epilogue ----
    if (tid < 384) Ls[tid] = Lacc;
    if (tid < 192) bnS[tid] = 0.f;
    // stage accumulators (overlaps A/B; safe after final sync)
#pragma unroll
    for (int mt = 0; mt < 2; mt++) {
        int row = wm * 32 + mt * 16 + gid;
#pragma unroll
        for (int nt = 0; nt < 9; nt++) {
            int cc = wn * 72 + nt * 8 + tq * 2;
            *(float2*)(stage + row * STG_PITCH + cc) = make_float2(acc[mt][nt][0], acc[mt][nt][1]);
            *(float2*)(stage + (row + 8) * STG_PITCH + cc) = make_float2(acc[mt][nt][2], acc[mt][nt][3]);
        }
    }
    __syncthreads();

    if (tid < 128) {
        float l0 = Ls[tid * 3 + 0] + g_lconst[0];
        float l1 = Ls[tid * 3 + 1] + g_lconst[1];
        float l2 = Ls[tid * 3 + 2] + g_lconst[2];
        float m = fmaxf(l0, fmaxf(l1, l2));
        float e0 = __expf(l0 - m), e1 = __expf(l1 - m), e2 = __expf(l2 - m);
        float inv = 1.f / (e0 + e1 + e2);
        Ws[tid * 3 + 0] = e0 * inv;
        Ws[tid * 3 + 1] = e1 * inv;
        Ws[tid * 3 + 2] = e2 * inv;
    }
    __syncthreads();

    if (tid < 384) {
        int c = tid % 96, q = tid / 96;
        float cs0 = g_cs[c], cs1 = g_cs[96 + c], cs2 = g_cs[192 + c];
        float fb = fus_b[c];
        float lsum = 0.f, lsq = 0.f;
        for (int r = q * 32; r < q * 32 + 32; r++) {
            int m = m0 + r;
            if (m >= NN) break;
            float s0 = Ws[r * 3 + 0], s1 = Ws[r * 3 + 1], s2 = Ws[r * 3 + 2];
            const float* f = stage + r * STG_PITCH;
            float h = s0 * (f[c] + cs0) + s1 * (f[96 + c] + cs1) + s2 * (f[192 + c] + cs2) + fb;
            g_h[(size_t)m * C + c] = h;
            lsum += h;
            lsq += h * h;
        }
        atomicAdd(&bnS[c], lsum);
        atomicAdd(&bnS[96 + c], lsq);
    }
    __syncthreads();
    if (tid < 96) {
        atomicAdd(&g_sum[tid], bnS[tid]);
        atomicAdd(&g_sumsq[tid], bnS[96 + tid]);
    }
#undef LOAD_A
#undef LOAD_B
}

// ---------------- BN finalize + normalize ----------------
__global__ void k_bnfin(const float* __restrict__ gamma, const float* __restrict__ beta) {
    int c = threadIdx.x;
    if (c >= C) return;
    float mean = g_sum[c] / (float)NN;
    float var = g_sumsq[c] / (float)NN - mean * mean;
    var = fmaxf(var, 0.f);
    float sc = gamma[c] * rsqrtf(var + BN_EPS);
    g_scale[c] = sc;
    g_shift[c] = beta[c] - mean * sc;
}

__global__ void k_norm(float* __restrict__ out) {
    int i = blockIdx.x * blockDim.x + threadIdx.x;
    if (i >= NN * C) return;
    int c = i % C;
    out[i] = fmaxf(fmaf(g_h[i], g_scale[c], g_shift[c]), 0.f);
}

// ---------------- launch ----------------
extern "C" void kernel_launch(void* const* d_in, const int* in_sizes, int n_in,
                              void* d_out, int out_size) {
    const float* x        = (const float*)d_in[0];
    const void* ei        = d_in[1];
    const float* w2       = (const float*)d_in[2];
    const float* b2       = (const float*)d_in[3];
    const float* w3       = (const float*)d_in[4];
    const float* b3       = (const float*)d_in[5];
    const float* w4       = (const float*)d_in[6];
    const float* b4       = (const float*)d_in[7];
    const float* attn_w   = (const float*)d_in[8];
    const float* attn_b   = (const float*)d_in[9];
    const float* fus_w    = (const float*)d_in[10];
    const float* fus_b    = (const float*)d_in[11];
    const float* bn_gamma = (const float*)d_in[12];
    const float* bn_beta  = (const float*)d_in[13];
    float* out = (float*)d_out;

    static int smem_set = 0;
    if (!smem_set) {
        cudaFuncSetAttribute(k_fused, cudaFuncAttributeMaxDynamicSharedMemorySize, FUSED_SMEM);
        smem_set = 1;
    }

    float* Tc = nullptr;
    cudaGetSymbolAddress((void**)&Tc, g_Tc);

    k_detect<<<1, 256>>>((const int*)ei);
    k_zero<<<(KW * FW + 255) / 256, 256>>>();
    k_edges<<<(NE + 255) / 256, 256>>>(ei);
    k_dis<<<(NN + 255) / 256, 256>>>();
    k_scan_local<<<49, 256>>>();
    k_scan_bsum<<<1, 32>>>();
    k_scan_add<<<(NN + 255) / 256, 256>>>();
    k_scatter<<<(NE + 255) / 256, 256>>>();
    k_precompU<<<9, 256>>>(w2, w3, w4, fus_w, attn_w);
    k_precomp_small<<<1, 288>>>(b2, b3, b4, fus_w, attn_w, attn_b);
    k_splitU16<<<(KW * FW + 255) / 256, 256>>>();

    // T1 = prop(T0); T2 = 2*prop(T1) - T0; T3 = 2*prop(T2) - T1
    k_spmm<<<6250, 256>>>(x, 96, nullptr, 0, Tc, 1);
    k_spmm<<<6250, 256>>>(Tc, TCW, x, 96, Tc + 96, 0);
    k_spmm<<<6250, 256>>>(Tc + 96, TCW, Tc, TCW, Tc + 192, 0);

    k_fused<<<TILES, 512, FUSED_SMEM>>>(x, fus_b);

    k_bnfin<<<1, 96>>>(bn_gamma, bn_beta);
    k_norm<<<(NN * C + 255) / 256, 256>>>(out);
}